// round 15
// baseline (speedup 1.0000x reference)
#include <cuda_runtime.h>
#include <cstdint>

// EmbedWeighted == out(B,D) = inputs(B,V) @ embeddings(V,D)
// R13 streaming fp16 GEMM + last-arrival reduction (zero spinning).
#define B_DIM 2048
#define V_DIM 2000
#define D_DIM 64
#define NSPLIT 8
#define KSPLIT 256            // splits 0..6: 256 (16 k16 steps); split 7: 208 (13)
#define NTHREADS 256
#define MTILE 128
#define NMTILE (B_DIM / MTILE)            // 16
#define ET_STR 132            // words per Et row (264 halves): 4 mod 32 -> banks ok

__device__ float g_partials[NSPLIT][B_DIM][D_DIM];   // 4 MB static scratch
__device__ unsigned g_arrive[NMTILE];                // zero-init, self-resetting

static __device__ __forceinline__ uint32_t smem_u32(const void* p) {
    return (uint32_t)__cvta_generic_to_shared(p);
}
static __device__ __forceinline__ uint32_t lds32(uint32_t a) {
    uint32_t v; asm("ld.shared.b32 %0, [%1];" : "=r"(v) : "r"(a)); return v;
}
static __device__ __forceinline__ uint32_t pack_h2(float lo, float hi) {
    uint32_t r;   // d.hi = cvt(%1), d.lo = cvt(%2)
    asm("cvt.rn.f16x2.f32 %0, %1, %2;" : "=r"(r) : "f"(hi), "f"(lo));
    return r;
}
// A stream load: 8B used, 256B prefetched into L2
static __device__ __forceinline__ float2 ldgA2(const float* p) {
    float2 v;
    asm("ld.global.nc.L2::256B.v2.f32 {%0,%1}, [%2];"
        : "=f"(v.x), "=f"(v.y) : "l"(p));
    return v;
}
static __device__ __forceinline__ float ldgE(const float* p) {
    float v;
    asm("ld.global.nc.L2::256B.f32 %0, [%1];" : "=f"(v) : "l"(p));
    return v;
}

// 256 threads, 8 warps; warp tile 16m x 64n. CTA tile 128x64. grid (8,16).
__global__ __launch_bounds__(NTHREADS, 2)
void embedweighted_last(const float* __restrict__ inp,
                        const float* __restrict__ emb,
                        float* __restrict__ out)
{
    __shared__ __align__(16) uint32_t Et[D_DIM * ET_STR];   // fp16 Et[n][k], 33.8 KB
    __shared__ unsigned s_last;

    const int ksplit = blockIdx.x;
    const int mtile  = blockIdx.y;
    const int m_base = mtile * MTILE;
    const int k_base = ksplit * KSPLIT;
    const int k_len  = (ksplit < NSPLIT - 1) ? KSPLIT : (V_DIM - (NSPLIT - 1) * KSPLIT);
    const int nk     = k_len >> 4;    // 16, last split 13 (exact)

    const int tid  = threadIdx.x;
    const int warp = tid >> 5;        // 0..7 -> rows m_base + warp*16 ..
    const int lane = tid & 31;
    const int g = lane >> 2;          // 0..7
    const int t = lane & 3;           // 0..3

    // ---- stage E once: Et[n][k] fp16, k zero-filled beyond V_DIM ----
    {
        const int en = tid & 63;      // n
        const int kb = tid >> 6;      // k-block 0..3 (64 k each)
        #pragma unroll
        for (int i = 0; i < 32; i++) {
            int k0 = k_base + kb * 64 + 2 * i;
            float f0 = (k0     < V_DIM) ? ldgE(emb + (size_t)k0 * D_DIM + en)       : 0.f;
            float f1 = (k0 + 1 < V_DIM) ? ldgE(emb + (size_t)(k0 + 1) * D_DIM + en) : 0.f;
            Et[en * ET_STR + kb * 32 + i] = pack_h2(f0, f1);
        }
    }

    // first two A k-steps prefetched into registers (independent of smem)
    const float* a0p = inp + (size_t)(m_base + warp * 16 + g) * V_DIM + k_base + 2 * t;
    const float* a8p = a0p + 8 * (size_t)V_DIM;
    float2 c0 = ldgA2(a0p),      c1 = ldgA2(a8p);
    float2 c2 = ldgA2(a0p + 8),  c3 = ldgA2(a8p + 8);
    float2 d0 = ldgA2(a0p + 16), d1 = ldgA2(a8p + 16);
    float2 d2 = ldgA2(a0p + 24), d3 = ldgA2(a8p + 24);

    __syncthreads();   // the ONLY gemm barrier: Et visible

    float acc[8][4];
    #pragma unroll
    for (int j = 0; j < 8; j++)
        #pragma unroll
        for (int r = 0; r < 4; r++) acc[j][r] = 0.0f;

    // ---- barrier-free mainloop: per-warp independent stream, distance-2 prefetch ----
    const uint32_t eb = smem_u32(Et) + (uint32_t)(g * ET_STR + t) * 4u;
    for (int ks = 0; ks < nk; ks++) {
        float2 n0 = c0, n1 = c1, n2 = c2, n3 = c3;   // default init (tail)
        if (ks + 2 < nk) {
            int off = (ks + 2) * 16;
            n0 = ldgA2(a0p + off);      n1 = ldgA2(a8p + off);
            n2 = ldgA2(a0p + off + 8);  n3 = ldgA2(a8p + off + 8);
        }
        const uint32_t a0 = pack_h2(c0.x, c0.y);
        const uint32_t a1 = pack_h2(c1.x, c1.y);
        const uint32_t a2 = pack_h2(c2.x, c2.y);
        const uint32_t a3 = pack_h2(c3.x, c3.y);

        const uint32_t ecur = eb + (uint32_t)(ks * 8) * 4u;
        #pragma unroll
        for (int nt = 0; nt < 8; nt++) {
            uint32_t b0 = lds32(ecur + (uint32_t)(nt * 8 * ET_STR) * 4u);
            uint32_t b1 = lds32(ecur + (uint32_t)(nt * 8 * ET_STR + 4) * 4u);
            asm volatile(
                "mma.sync.aligned.m16n8k16.row.col.f32.f16.f16.f32 "
                "{%0,%1,%2,%3}, {%4,%5,%6,%7}, {%8,%9}, {%0,%1,%2,%3};"
                : "+f"(acc[nt][0]), "+f"(acc[nt][1]),
                  "+f"(acc[nt][2]), "+f"(acc[nt][3])
                : "r"(a0), "r"(a1), "r"(a2), "r"(a3), "r"(b0), "r"(b1));
        }
        c0 = d0; c1 = d1; c2 = d2; c3 = d3;
        d0 = n0; d1 = n1; d2 = n2; d3 = n3;
    }

    // ---- write 16x64 fp32 partial strip per warp ----
    {
        float* pp = &g_partials[ksplit][m_base + warp * 16][0];
        #pragma unroll
        for (int nt = 0; nt < 8; nt++) {
            int n0c = nt * 8 + 2 * t;
            pp[g * D_DIM + n0c]           = acc[nt][0];
            pp[g * D_DIM + n0c + 1]       = acc[nt][1];
            pp[(g + 8) * D_DIM + n0c]     = acc[nt][2];
            pp[(g + 8) * D_DIM + n0c + 1] = acc[nt][3];
        }
    }

    // ---- last-arrival reduction: NO spinning, non-last CTAs exit now ----
    __syncthreads();   // all partial stores of this CTA issued
    if (tid == 0) {
        __threadfence();                               // release partial stores
        unsigned old = atomicAdd(&g_arrive[mtile], 1u);
        unsigned last = (old == NSPLIT - 1) ? 1u : 0u;
        if (last) {    // acquire: pair with the other 7 CTAs' release fences
            unsigned v;
            asm volatile("ld.acquire.gpu.u32 %0, [%1];" : "=r"(v) : "l"(&g_arrive[mtile]));
        }
        s_last = last;
    }
    __syncthreads();   // propagate s_last + tid0's acquire CTA-wide

    if (s_last) {
        // This (single) CTA reduces the whole mtile: 2048 float4, 8 per thread.
        const float4* p = reinterpret_cast<const float4*>(&g_partials[0][0][0]);
        float4* o = reinterpret_cast<float4*>(out);
        #pragma unroll
        for (int i = 0; i < 8; i++) {
            int off = m_base * (D_DIM / 4) + tid + i * NTHREADS;
            float4 s = p[off];
            #pragma unroll
            for (int sp = 1; sp < NSPLIT; sp++) {   // fixed order -> deterministic
                float4 v = p[(size_t)sp * (B_DIM * D_DIM / 4) + off];
                s.x += v.x; s.y += v.y; s.z += v.z; s.w += v.w;
            }
            o[off] = s;
        }
        __syncthreads();
        if (tid == 0) atomicExch(&g_arrive[mtile], 0u);   // reset for graph replay
    }
}

extern "C" void kernel_launch(void* const* d_in, const int* in_sizes, int n_in,
                              void* d_out, int out_size)
{
    const float* inputs     = (const float*)d_in[0];   // (B, V) fp32
    const float* embeddings = (const float*)d_in[1];   // (V, D) fp32
    float* out = (float*)d_out;                        // (B, D) fp32

    dim3 grid(NSPLIT, NMTILE);   // 128 CTAs; no co-residency requirement (no waits)
    embedweighted_last<<<grid, NTHREADS>>>(inputs, embeddings, out);
}

// round 16
// speedup vs baseline: 1.0056x; 1.0056x over previous
#include <cuda_runtime.h>
#include <cstdint>

// EmbedWeighted == out(B,D) = inputs(B,V) @ embeddings(V,D)
// R13 streaming fp16 GEMM, re-tiled: warp 16m x 32n, CTA 64x64, 256 CTAs.
#define B_DIM 2048
#define V_DIM 2000
#define D_DIM 64
#define NSPLIT 8
#define KSPLIT 256            // splits 0..6: 256 (16 k16 steps); split 7: 208 (13)
#define NTHREADS 256
#define MTILE 64
#define NMTILE (B_DIM / MTILE)            // 32
#define ET_STR 132            // words per Et row (264 halves): 4 mod 32 -> banks ok

__device__ float g_partials[NSPLIT][B_DIM][D_DIM];   // 4 MB static scratch
__device__ unsigned g_arrive[NMTILE];                // zero-init, self-resetting
__device__ unsigned g_done[NMTILE];

static __device__ __forceinline__ uint32_t smem_u32(const void* p) {
    return (uint32_t)__cvta_generic_to_shared(p);
}
static __device__ __forceinline__ uint32_t lds32(uint32_t a) {
    uint32_t v; asm("ld.shared.b32 %0, [%1];" : "=r"(v) : "r"(a)); return v;
}
static __device__ __forceinline__ uint32_t pack_h2(float lo, float hi) {
    uint32_t r;   // d.hi = cvt(%1), d.lo = cvt(%2)
    asm("cvt.rn.f16x2.f32 %0, %1, %2;" : "=r"(r) : "f"(hi), "f"(lo));
    return r;
}
// A stream load: 8B used, 256B prefetched into L2
static __device__ __forceinline__ float2 ldgA2(const float* p) {
    float2 v;
    asm("ld.global.nc.L2::256B.v2.f32 {%0,%1}, [%2];"
        : "=f"(v.x), "=f"(v.y) : "l"(p));
    return v;
}
static __device__ __forceinline__ float ldgE(const float* p) {
    float v;
    asm("ld.global.nc.L2::256B.f32 %0, [%1];" : "=f"(v) : "l"(p));
    return v;
}

// 256 threads, 8 warps; warp tile 16m x 32n. CTA tile 64x64.
// grid (8, 32) = 256 CTAs, occ 2 -> all co-resident (capacity 296).
__global__ __launch_bounds__(NTHREADS, 2)
void embedweighted_wt32(const float* __restrict__ inp,
                        const float* __restrict__ emb,
                        float* __restrict__ out)
{
    __shared__ __align__(16) uint32_t Et[D_DIM * ET_STR];   // fp16 Et[n][k], 33.8 KB

    const int ksplit = blockIdx.x;
    const int mtile  = blockIdx.y;
    const int m_base = mtile * MTILE;
    const int k_base = ksplit * KSPLIT;
    const int k_len  = (ksplit < NSPLIT - 1) ? KSPLIT : (V_DIM - (NSPLIT - 1) * KSPLIT);
    const int nk     = k_len >> 4;    // 16, last split 13 (exact)

    const int tid  = threadIdx.x;
    const int warp = tid >> 5;
    const int lane = tid & 31;
    const int g = lane >> 2;          // 0..7
    const int t = lane & 3;           // 0..3
    const int warp_m = warp & 3;      // m-strip 0..3 (16 rows each)
    const int warp_n = warp >> 2;     // n-half 0..1 (32 cols each)

    // ---- stage E once: Et[n][k] fp16, k zero-filled beyond V_DIM ----
    {
        const int en = tid & 63;      // n
        const int kb = tid >> 6;      // k-block 0..3 (64 k each)
        #pragma unroll
        for (int i = 0; i < 32; i++) {
            int k0 = k_base + kb * 64 + 2 * i;
            float f0 = (k0     < V_DIM) ? ldgE(emb + (size_t)k0 * D_DIM + en)       : 0.f;
            float f1 = (k0 + 1 < V_DIM) ? ldgE(emb + (size_t)(k0 + 1) * D_DIM + en) : 0.f;
            Et[en * ET_STR + kb * 32 + i] = pack_h2(f0, f1);
        }
    }

    // first two A k-steps prefetched into registers (independent of smem)
    const float* a0p = inp + (size_t)(m_base + warp_m * 16 + g) * V_DIM + k_base + 2 * t;
    const float* a8p = a0p + 8 * (size_t)V_DIM;
    float2 c0 = ldgA2(a0p),      c1 = ldgA2(a8p);
    float2 c2 = ldgA2(a0p + 8),  c3 = ldgA2(a8p + 8);
    float2 d0 = ldgA2(a0p + 16), d1 = ldgA2(a8p + 16);
    float2 d2 = ldgA2(a0p + 24), d3 = ldgA2(a8p + 24);

    __syncthreads();   // the ONLY gemm barrier: Et visible

    float acc[4][4];
    #pragma unroll
    for (int j = 0; j < 4; j++)
        #pragma unroll
        for (int r = 0; r < 4; r++) acc[j][r] = 0.0f;

    // ---- barrier-free mainloop: half the per-step work of R13 ----
    const uint32_t eb = smem_u32(Et)
                      + (uint32_t)((warp_n * 32 + g) * ET_STR + t) * 4u;
    for (int ks = 0; ks < nk; ks++) {
        float2 n0 = c0, n1 = c1, n2 = c2, n3 = c3;   // default init (tail)
        if (ks + 2 < nk) {
            int off = (ks + 2) * 16;
            n0 = ldgA2(a0p + off);      n1 = ldgA2(a8p + off);
            n2 = ldgA2(a0p + off + 8);  n3 = ldgA2(a8p + off + 8);
        }
        const uint32_t a0 = pack_h2(c0.x, c0.y);
        const uint32_t a1 = pack_h2(c1.x, c1.y);
        const uint32_t a2 = pack_h2(c2.x, c2.y);
        const uint32_t a3 = pack_h2(c3.x, c3.y);

        const uint32_t ecur = eb + (uint32_t)(ks * 8) * 4u;
        #pragma unroll
        for (int nt = 0; nt < 4; nt++) {
            uint32_t b0 = lds32(ecur + (uint32_t)(nt * 8 * ET_STR) * 4u);
            uint32_t b1 = lds32(ecur + (uint32_t)(nt * 8 * ET_STR + 4) * 4u);
            asm volatile(
                "mma.sync.aligned.m16n8k16.row.col.f32.f16.f16.f32 "
                "{%0,%1,%2,%3}, {%4,%5,%6,%7}, {%8,%9}, {%0,%1,%2,%3};"
                : "+f"(acc[nt][0]), "+f"(acc[nt][1]),
                  "+f"(acc[nt][2]), "+f"(acc[nt][3])
                : "r"(a0), "r"(a1), "r"(a2), "r"(a3), "r"(b0), "r"(b1));
        }
        c0 = d0; c1 = d1; c2 = d2; c3 = d3;
        d0 = n0; d1 = n1; d2 = n2; d3 = n3;
    }

    // ---- write 16x32 fp32 partial strip per warp ----
    {
        float* pp = &g_partials[ksplit][m_base + warp_m * 16][0];
        #pragma unroll
        for (int nt = 0; nt < 4; nt++) {
            int n0c = warp_n * 32 + nt * 8 + 2 * t;
            pp[g * D_DIM + n0c]           = acc[nt][0];
            pp[g * D_DIM + n0c + 1]       = acc[nt][1];
            pp[(g + 8) * D_DIM + n0c]     = acc[nt][2];
            pp[(g + 8) * D_DIM + n0c + 1] = acc[nt][3];
        }
    }

    // ---- fused deterministic split-K reduction (all 256 CTAs co-resident) ----
    __syncthreads();
    if (tid == 0) {
        __threadfence();                       // release partial stores
        atomicAdd(&g_arrive[mtile], 1u);
        unsigned v;
        do {
            asm volatile("ld.acquire.gpu.u32 %0, [%1];" : "=r"(v) : "l"(&g_arrive[mtile]));
            if (v >= NSPLIT) break;
            __nanosleep(64);
        } while (true);
    }
    __syncthreads();   // propagate tid0's acquire CTA-wide

    if (tid < 128) {   // this CTA reduces rows [m_base + ksplit*8, +8): 128 float4
        int r = tid >> 4, q = tid & 15;
        int off = (m_base + ksplit * 8 + r) * (D_DIM / 4) + q;
        const float4* p = reinterpret_cast<const float4*>(&g_partials[0][0][0]);
        float4 s = p[off];
        #pragma unroll
        for (int sp = 1; sp < NSPLIT; sp++) {   // fixed order -> deterministic
            float4 v = p[(size_t)sp * (B_DIM * D_DIM / 4) + off];
            s.x += v.x; s.y += v.y; s.z += v.z; s.w += v.w;
        }
        reinterpret_cast<float4*>(out)[off] = s;
    }

    __syncthreads();
    if (tid == 0) {   // reset counters for graph replay
        unsigned d = atomicAdd(&g_done[mtile], 1u);
        if (d == NSPLIT - 1) {
            atomicExch(&g_arrive[mtile], 0u);
            atomicExch(&g_done[mtile], 0u);
        }
    }
}

extern "C" void kernel_launch(void* const* d_in, const int* in_sizes, int n_in,
                              void* d_out, int out_size)
{
    const float* inputs     = (const float*)d_in[0];   // (B, V) fp32
    const float* embeddings = (const float*)d_in[1];   // (V, D) fp32
    float* out = (float*)d_out;                        // (B, D) fp32

    dim3 grid(NSPLIT, NMTILE);   // 256 CTAs, occ 2 -> all co-resident
    embedweighted_wt32<<<grid, NTHREADS>>>(inputs, embeddings, out);
}

// round 17
// speedup vs baseline: 1.3400x; 1.3325x over previous
#include <cuda_runtime.h>
#include <cstdint>

// EmbedWeighted == out(B,D) = inputs(B,V) @ embeddings(V,D)
// R13 champion + reordered prologue, distance-3 A prefetch, batched E-stage.
#define B_DIM 2048
#define V_DIM 2000
#define D_DIM 64
#define NSPLIT 8
#define KSPLIT 256            // splits 0..6: 256 (16 k16 steps); split 7: 208 (13)
#define NTHREADS 256
#define MTILE 128
#define NMTILE (B_DIM / MTILE)            // 16
#define ET_STR 132            // words per Et row (264 halves): 4 mod 32 -> banks ok

__device__ float g_partials[NSPLIT][B_DIM][D_DIM];   // 4 MB static scratch
__device__ unsigned g_arrive[NMTILE];                // zero-init, self-resetting
__device__ unsigned g_done[NMTILE];

static __device__ __forceinline__ uint32_t smem_u32(const void* p) {
    return (uint32_t)__cvta_generic_to_shared(p);
}
static __device__ __forceinline__ uint32_t lds32(uint32_t a) {
    uint32_t v; asm("ld.shared.b32 %0, [%1];" : "=r"(v) : "r"(a)); return v;
}
static __device__ __forceinline__ uint32_t pack_h2(float lo, float hi) {
    uint32_t r;   // d.hi = cvt(%1), d.lo = cvt(%2)
    asm("cvt.rn.f16x2.f32 %0, %1, %2;" : "=r"(r) : "f"(hi), "f"(lo));
    return r;
}
// A stream load: 8B used, 256B prefetched into L2
static __device__ __forceinline__ float2 ldgA2(const float* p) {
    float2 v;
    asm("ld.global.nc.L2::256B.v2.f32 {%0,%1}, [%2];"
        : "=f"(v.x), "=f"(v.y) : "l"(p));
    return v;
}
static __device__ __forceinline__ float ldgE(const float* p) {
    float v;
    asm("ld.global.nc.L2::256B.f32 %0, [%1];" : "=f"(v) : "l"(p));
    return v;
}

// 256 threads, 8 warps; warp tile 16m x 64n. CTA tile 128x64. grid (8,16).
__global__ __launch_bounds__(NTHREADS, 2)
void embedweighted_pf3(const float* __restrict__ inp,
                       const float* __restrict__ emb,
                       float* __restrict__ out)
{
    __shared__ __align__(16) uint32_t Et[D_DIM * ET_STR];   // fp16 Et[n][k], 33.8 KB

    const int ksplit = blockIdx.x;
    const int mtile  = blockIdx.y;
    const int m_base = mtile * MTILE;
    const int k_base = ksplit * KSPLIT;
    const int k_len  = (ksplit < NSPLIT - 1) ? KSPLIT : (V_DIM - (NSPLIT - 1) * KSPLIT);
    const int nk     = k_len >> 4;    // 16, last split 13 (exact)

    const int tid  = threadIdx.x;
    const int warp = tid >> 5;        // 0..7 -> rows m_base + warp*16 ..
    const int lane = tid & 31;
    const int g = lane >> 2;          // 0..7
    const int t = lane & 3;           // 0..3

    // ---- A prologue FIRST: 3 k-steps in flight before E-stage begins ----
    const float* a0p = inp + (size_t)(m_base + warp * 16 + g) * V_DIM + k_base + 2 * t;
    const float* a8p = a0p + 8 * (size_t)V_DIM;
    float2 c0 = ldgA2(a0p),      c1 = ldgA2(a8p);
    float2 c2 = ldgA2(a0p + 8),  c3 = ldgA2(a8p + 8);
    float2 d0 = ldgA2(a0p + 16), d1 = ldgA2(a8p + 16);
    float2 d2 = ldgA2(a0p + 24), d3 = ldgA2(a8p + 24);
    float2 e0 = ldgA2(a0p + 32), e1 = ldgA2(a8p + 32);
    float2 e2 = ldgA2(a0p + 40), e3 = ldgA2(a8p + 40);

    // ---- stage E (batched: 16 loads front-issued, then 8 pack+STS) ----
    {
        const int en = tid & 63;      // n
        const int kb = tid >> 6;      // k-block 0..3 (64 k each)
        #pragma unroll
        for (int blk = 0; blk < 4; blk++) {
            float f[16];
            #pragma unroll
            for (int i = 0; i < 16; i++) {
                int k0 = k_base + kb * 64 + blk * 16 + i;
                f[i] = (k0 < V_DIM) ? ldgE(emb + (size_t)k0 * D_DIM + en) : 0.f;
            }
            #pragma unroll
            for (int i = 0; i < 8; i++)
                Et[en * ET_STR + kb * 32 + blk * 8 + i] = pack_h2(f[2 * i], f[2 * i + 1]);
        }
    }
    __syncthreads();   // the ONLY gemm barrier: Et visible

    float acc[8][4];
    #pragma unroll
    for (int j = 0; j < 8; j++)
        #pragma unroll
        for (int r = 0; r < 4; r++) acc[j][r] = 0.0f;

    // ---- barrier-free mainloop: distance-3 A prefetch ----
    const uint32_t eb = smem_u32(Et) + (uint32_t)(g * ET_STR + t) * 4u;
    for (int ks = 0; ks < nk; ks++) {
        float2 n0 = c0, n1 = c1, n2 = c2, n3 = c3;   // default init (tail)
        if (ks + 3 < nk) {
            int off = (ks + 3) * 16;
            n0 = ldgA2(a0p + off);      n1 = ldgA2(a8p + off);
            n2 = ldgA2(a0p + off + 8);  n3 = ldgA2(a8p + off + 8);
        }
        const uint32_t a0 = pack_h2(c0.x, c0.y);
        const uint32_t a1 = pack_h2(c1.x, c1.y);
        const uint32_t a2 = pack_h2(c2.x, c2.y);
        const uint32_t a3 = pack_h2(c3.x, c3.y);

        const uint32_t ecur = eb + (uint32_t)(ks * 8) * 4u;
        #pragma unroll
        for (int nt = 0; nt < 8; nt++) {
            uint32_t b0 = lds32(ecur + (uint32_t)(nt * 8 * ET_STR) * 4u);
            uint32_t b1 = lds32(ecur + (uint32_t)(nt * 8 * ET_STR + 4) * 4u);
            asm volatile(
                "mma.sync.aligned.m16n8k16.row.col.f32.f16.f16.f32 "
                "{%0,%1,%2,%3}, {%4,%5,%6,%7}, {%8,%9}, {%0,%1,%2,%3};"
                : "+f"(acc[nt][0]), "+f"(acc[nt][1]),
                  "+f"(acc[nt][2]), "+f"(acc[nt][3])
                : "r"(a0), "r"(a1), "r"(a2), "r"(a3), "r"(b0), "r"(b1));
        }
        c0 = d0; c1 = d1; c2 = d2; c3 = d3;
        d0 = e0; d1 = e1; d2 = e2; d3 = e3;
        e0 = n0; e1 = n1; e2 = n2; e3 = n3;
    }

    // ---- write 16x64 fp32 partial strip per warp ----
    {
        float* pp = &g_partials[ksplit][m_base + warp * 16][0];
        #pragma unroll
        for (int nt = 0; nt < 8; nt++) {
            int n0c = nt * 8 + 2 * t;
            pp[g * D_DIM + n0c]           = acc[nt][0];
            pp[g * D_DIM + n0c + 1]       = acc[nt][1];
            pp[(g + 8) * D_DIM + n0c]     = acc[nt][2];
            pp[(g + 8) * D_DIM + n0c + 1] = acc[nt][3];
        }
    }

    // ---- fused deterministic split-K reduction (all 128 CTAs co-resident) ----
    __syncthreads();
    if (tid == 0) {
        __threadfence();                       // release partial stores
        atomicAdd(&g_arrive[mtile], 1u);
        unsigned v;
        do {
            asm volatile("ld.acquire.gpu.u32 %0, [%1];" : "=r"(v) : "l"(&g_arrive[mtile]));
            if (v >= NSPLIT) break;
            __nanosleep(64);
        } while (true);
    }
    __syncthreads();   // propagate tid0's acquire CTA-wide

    {   // this CTA reduces rows [m_base + ksplit*16, +16): 256 float4, 1/thread
        int r = tid >> 4, q = tid & 15;
        int off = (m_base + ksplit * 16 + r) * (D_DIM / 4) + q;
        const float4* p = reinterpret_cast<const float4*>(&g_partials[0][0][0]);
        float4 s = p[off];
        #pragma unroll
        for (int sp = 1; sp < NSPLIT; sp++) {   // fixed order -> deterministic
            float4 v = p[(size_t)sp * (B_DIM * D_DIM / 4) + off];
            s.x += v.x; s.y += v.y; s.z += v.z; s.w += v.w;
        }
        reinterpret_cast<float4*>(out)[off] = s;
    }

    __syncthreads();
    if (tid == 0) {   // reset counters for graph replay
        unsigned d = atomicAdd(&g_done[mtile], 1u);
        if (d == NSPLIT - 1) {
            atomicExch(&g_arrive[mtile], 0u);
            atomicExch(&g_done[mtile], 0u);
        }
    }
}

extern "C" void kernel_launch(void* const* d_in, const int* in_sizes, int n_in,
                              void* d_out, int out_size)
{
    const float* inputs     = (const float*)d_in[0];   // (B, V) fp32
    const float* embeddings = (const float*)d_in[1];   // (V, D) fp32
    float* out = (float*)d_out;                        // (B, D) fp32

    dim3 grid(NSPLIT, NMTILE);   // 128 CTAs == one wave, all co-resident
    embedweighted_pf3<<<grid, NTHREADS>>>(inputs, embeddings, out);
}